// round 1
// baseline (speedup 1.0000x reference)
#include <cuda_runtime.h>
#include <cstdint>

#define BATCH 4096
#define TT    140
#define HH    128
#define G4    512
#define BT    32          // batches per CTA
#define NCTA  128
#define NTHR  256
#define KC    32          // k per streamed chunk
#define SMEM_FLOATS (2*KC*G4 + BT*HH + BT*TT)
#define SMEM_BYTES  (SMEM_FLOATS*4)

// Persistent device scratch (allowed: __device__ globals, no runtime alloc)
__device__ float g_Wt[HH*G4];    // W_hh transposed: [k][j]
__device__ float g_W1t[HH*HH];   // W1 transposed:   [k][n]
__device__ float g_bias[G4];     // b_ih + b_hh

// ---------- small helpers ----------
__device__ __forceinline__ unsigned long long pack2(float lo, float hi){
    unsigned long long r;
    asm("mov.b64 %0,{%1,%2};" : "=l"(r) : "f"(lo), "f"(hi));
    return r;
}
__device__ __forceinline__ unsigned long long packdup(float v){
    unsigned long long r;
    asm("mov.b64 %0,{%1,%1};" : "=l"(r) : "f"(v));
    return r;
}
__device__ __forceinline__ void unpack2(unsigned long long v, float& lo, float& hi){
    asm("mov.b64 {%0,%1},%2;" : "=f"(lo), "=f"(hi) : "l"(v));
}
__device__ __forceinline__ unsigned long long ffma2(unsigned long long a,
                                                    unsigned long long b,
                                                    unsigned long long c){
    unsigned long long d;
    asm("fma.rn.f32x2 %0,%1,%2,%3;" : "=l"(d) : "l"(a), "l"(b), "l"(c));
    return d;
}
// sigmoid(x) = 1/(1+2^(-x*log2e)) via ex2.approx + rcp.approx (~1e-7 accurate)
__device__ __forceinline__ float fast_sigmoid(float x){
    float e, r;
    asm("ex2.approx.f32 %0,%1;" : "=f"(e) : "f"(-1.4426950408889634f * x));
    asm("rcp.approx.f32 %0,%1;" : "=f"(r) : "f"(1.0f + e));
    return r;
}
// tanh(x) = 1 - 2/(2^(2x*log2e)+1)
__device__ __forceinline__ float fast_tanh(float x){
    float e, r;
    asm("ex2.approx.f32 %0,%1;" : "=f"(e) : "f"(2.8853900817779268f * x));
    asm("rcp.approx.f32 %0,%1;" : "=f"(r) : "f"(1.0f + e));
    return 1.0f - 2.0f * r;
}
__device__ __forceinline__ void cp_async16(void* smem_ptr, const void* gmem_ptr){
    unsigned s = (unsigned)__cvta_generic_to_shared(smem_ptr);
    asm volatile("cp.async.cg.shared.global [%0],[%1],16;" :: "r"(s), "l"(gmem_ptr));
}
__device__ __forceinline__ void cp_commit(){
    asm volatile("cp.async.commit_group;" ::: "memory");
}
template<int N>
__device__ __forceinline__ void cp_wait(){
    asm volatile("cp.async.wait_group %0;" :: "n"(N) : "memory");
}

__device__ __forceinline__ void copy_chunk(float* wbuf, int chunk, int buf, int tid){
    const float* src = g_Wt + chunk * (KC * G4);
    float* dst = wbuf + buf * (KC * G4);
    #pragma unroll
    for (int i = 0; i < (KC*G4) / (4*NTHR); i++){
        int idx = (tid + i * NTHR) * 4;
        cp_async16(dst + idx, src + idx);
    }
}

// ---------- prep: transpose W_hh, W1; sum biases ----------
__global__ void prep_kernel(const float* __restrict__ Whh,
                            const float* __restrict__ bih,
                            const float* __restrict__ bhh,
                            const float* __restrict__ W1){
    int i = blockIdx.x * blockDim.x + threadIdx.x;
    int stride = gridDim.x * blockDim.x;
    for (int idx = i; idx < G4*HH; idx += stride){
        int j = idx / HH, k = idx % HH;
        g_Wt[k*G4 + j] = Whh[idx];
    }
    for (int idx = i; idx < HH*HH; idx += stride){
        int n = idx / HH, k = idx % HH;
        g_W1t[k*HH + n] = W1[idx];
    }
    for (int idx = i; idx < G4; idx += stride)
        g_bias[idx] = bih[idx] + bhh[idx];
}

// ---------- main persistent LSTM kernel ----------
__global__ __launch_bounds__(NTHR, 1)
void lstm_kernel(const float* __restrict__ x,
                 const float* __restrict__ Wih,
                 const float* __restrict__ b1,
                 const float* __restrict__ W2,
                 const float* __restrict__ b2,
                 float* __restrict__ out){
    extern __shared__ float smem[];
    float* wbuf = smem;                    // [2][KC][G4]
    float* h_sh = smem + 2*KC*G4;          // [BT][HH]
    float* x_sh = h_sh + BT*HH;            // [BT][TT] (reused as r1 scratch later)

    const int tid = threadIdx.x;
    const int bg  = tid >> 5;              // 0..7   batch group
    const int gg  = tid & 31;              // 0..31  gate/unit group
    const int b0  = blockIdx.x * BT;

    // stage x tile: x[(b0+b)*TT + t] -> x_sh[b*TT + t]
    for (int idx = tid; idx < BT*TT; idx += NTHR){
        int b = idx / TT, t = idx % TT;
        x_sh[idx] = x[(size_t)(b0 + b) * TT + t];
    }
    // zero h
    for (int idx = tid; idx < BT*HH; idx += NTHR) h_sh[idx] = 0.0f;

    // per-thread constants: gate columns j = q*128 + gg*4 + {0..3}
    unsigned long long bias2[4][2], win2[4][2];
    #pragma unroll
    for (int q = 0; q < 4; q++)
        #pragma unroll
        for (int up = 0; up < 2; up++){
            int j = q*HH + gg*4 + up*2;
            bias2[q][up] = pack2(g_bias[j], g_bias[j+1]);
            win2[q][up]  = pack2(Wih[j],    Wih[j+1]);
        }
    float c_reg[4][4];
    #pragma unroll
    for (int bi = 0; bi < 4; bi++)
        #pragma unroll
        for (int ui = 0; ui < 4; ui++) c_reg[bi][ui] = 0.0f;

    const float* hrow[4];
    #pragma unroll
    for (int bi = 0; bi < 4; bi++) hrow[bi] = h_sh + (4*bg + bi) * HH;

    __syncthreads();

    // prologue: prefetch chunks 0,1
    copy_chunk(wbuf, 0, 0, tid); cp_commit();
    copy_chunk(wbuf, 1, 1, tid); cp_commit();

    for (int t = 0; t < TT; t++){
        // init accumulators: bias + x_t * w_in
        unsigned long long acc[4][4][2];
        #pragma unroll
        for (int bi = 0; bi < 4; bi++){
            unsigned long long x2 = packdup(x_sh[(4*bg + bi)*TT + t]);
            #pragma unroll
            for (int q = 0; q < 4; q++)
                #pragma unroll
                for (int up = 0; up < 2; up++)
                    acc[bi][q][up] = ffma2(x2, win2[q][up], bias2[q][up]);
        }

        // GEMM: gates += h @ W_hh^T, streamed in 4 k-chunks
        for (int c = 0; c < 4; c++){
            cp_wait<1>();
            __syncthreads();
            const float* wb = wbuf + (c & 1) * (KC * G4);
            const int kb = c * KC;
            #pragma unroll 4
            for (int kk = 0; kk < KC; kk++){
                const int k = kb + kk;
                const float* wr = wb + kk*G4 + gg*4;
                ulonglong2 w0 = *(const ulonglong2*)(wr);
                ulonglong2 w1 = *(const ulonglong2*)(wr + HH);
                ulonglong2 w2 = *(const ulonglong2*)(wr + 2*HH);
                ulonglong2 w3 = *(const ulonglong2*)(wr + 3*HH);
                #pragma unroll
                for (int bi = 0; bi < 4; bi++){
                    unsigned long long h2 = packdup(hrow[bi][k]);
                    acc[bi][0][0] = ffma2(h2, w0.x, acc[bi][0][0]);
                    acc[bi][0][1] = ffma2(h2, w0.y, acc[bi][0][1]);
                    acc[bi][1][0] = ffma2(h2, w1.x, acc[bi][1][0]);
                    acc[bi][1][1] = ffma2(h2, w1.y, acc[bi][1][1]);
                    acc[bi][2][0] = ffma2(h2, w2.x, acc[bi][2][0]);
                    acc[bi][2][1] = ffma2(h2, w2.y, acc[bi][2][1]);
                    acc[bi][3][0] = ffma2(h2, w3.x, acc[bi][3][0]);
                    acc[bi][3][1] = ffma2(h2, w3.y, acc[bi][3][1]);
                }
            }
            __syncthreads();
            copy_chunk(wbuf, (c + 2) & 3, c & 1, tid);
            cp_commit();
        }

        // LSTM elementwise update (fully thread-local: units u = gg*4 + {0..3})
        #pragma unroll
        for (int bi = 0; bi < 4; bi++){
            float hv[4];
            #pragma unroll
            for (int up = 0; up < 2; up++){
                float i0,i1,f0,f1,g0,g1,o0,o1;
                unpack2(acc[bi][0][up], i0, i1);
                unpack2(acc[bi][1][up], f0, f1);
                unpack2(acc[bi][2][up], g0, g1);
                unpack2(acc[bi][3][up], o0, o1);
                {
                    float iv = fast_sigmoid(i0), fv = fast_sigmoid(f0);
                    float gv = fast_tanh(g0),    ov = fast_sigmoid(o0);
                    float cv = fv * c_reg[bi][2*up+0] + iv * gv;
                    c_reg[bi][2*up+0] = cv;
                    hv[2*up+0] = ov * fast_tanh(cv);
                }
                {
                    float iv = fast_sigmoid(i1), fv = fast_sigmoid(f1);
                    float gv = fast_tanh(g1),    ov = fast_sigmoid(o1);
                    float cv = fv * c_reg[bi][2*up+1] + iv * gv;
                    c_reg[bi][2*up+1] = cv;
                    hv[2*up+1] = ov * fast_tanh(cv);
                }
            }
            // conflict-free STS.128 into batch-major h
            *(float4*)&h_sh[(4*bg + bi)*HH + gg*4] =
                make_float4(hv[0], hv[1], hv[2], hv[3]);
        }
        __syncthreads();
    }

    cp_wait<0>();
    __syncthreads();

    // ---------- fused MLP head: r1 = relu(h@W1^T + b1) ----------
    float r1a[4][4];
    {
        float bb[4];
        #pragma unroll
        for (int ni = 0; ni < 4; ni++) bb[ni] = b1[gg*4 + ni];
        #pragma unroll
        for (int bi = 0; bi < 4; bi++)
            #pragma unroll
            for (int ni = 0; ni < 4; ni++) r1a[bi][ni] = bb[ni];
    }
    for (int k = 0; k < HH; k++){
        float4 w = *(const float4*)&g_W1t[k*HH + gg*4];
        #pragma unroll
        for (int bi = 0; bi < 4; bi++){
            float hb = hrow[bi][k];
            r1a[bi][0] = fmaf(hb, w.x, r1a[bi][0]);
            r1a[bi][1] = fmaf(hb, w.y, r1a[bi][1]);
            r1a[bi][2] = fmaf(hb, w.z, r1a[bi][2]);
            r1a[bi][3] = fmaf(hb, w.w, r1a[bi][3]);
        }
    }
    __syncthreads();   // everyone done reading h_sh & x_sh
    // reuse x_sh as r1 scratch [BT][HH]
    #pragma unroll
    for (int bi = 0; bi < 4; bi++){
        float4 v = make_float4(fmaxf(r1a[bi][0], 0.f), fmaxf(r1a[bi][1], 0.f),
                               fmaxf(r1a[bi][2], 0.f), fmaxf(r1a[bi][3], 0.f));
        *(float4*)&x_sh[(4*bg + bi)*HH + gg*4] = v;
    }
    // stage W2 (5x128) into wbuf
    for (int idx = tid; idx < 5*HH; idx += NTHR) wbuf[idx] = W2[idx];
    __syncthreads();

    // ---------- r2 = r1@W2^T + b2; log_softmax ----------
    if (tid < BT){
        const int b = tid;
        float r2[5];
        #pragma unroll
        for (int o = 0; o < 5; o++) r2[o] = b2[o];
        for (int kk = 0; kk < HH; kk++){
            int k = (kk + b*4) & (HH - 1);       // stagger to avoid smem conflicts
            float v = x_sh[b*HH + k];
            #pragma unroll
            for (int o = 0; o < 5; o++) r2[o] = fmaf(v, wbuf[o*HH + k], r2[o]);
        }
        float m = r2[0];
        #pragma unroll
        for (int o = 1; o < 5; o++) m = fmaxf(m, r2[o]);
        float s = 0.f;
        #pragma unroll
        for (int o = 0; o < 5; o++) s += __expf(r2[o] - m);
        float l = m + __logf(s);
        #pragma unroll
        for (int o = 0; o < 5; o++)
            out[(size_t)(b0 + b)*5 + o] = r2[o] - l;
    }
}

extern "C" void kernel_launch(void* const* d_in, const int* in_sizes, int n_in,
                              void* d_out, int out_size){
    const float* x   = (const float*)d_in[0];
    const float* Wih = (const float*)d_in[1];
    const float* Whh = (const float*)d_in[2];
    const float* bih = (const float*)d_in[3];
    const float* bhh = (const float*)d_in[4];
    const float* W1  = (const float*)d_in[5];
    const float* b1  = (const float*)d_in[6];
    const float* W2  = (const float*)d_in[7];
    const float* b2  = (const float*)d_in[8];
    float* out = (float*)d_out;

    prep_kernel<<<64, 256>>>(Whh, bih, bhh, W1);

    cudaFuncSetAttribute(lstm_kernel,
                         cudaFuncAttributeMaxDynamicSharedMemorySize, SMEM_BYTES);
    lstm_kernel<<<NCTA, NTHR, SMEM_BYTES>>>(x, Wih, b1, W2, b2, out);
}